// round 13
// baseline (speedup 1.0000x reference)
#include <cuda_runtime.h>
#include <cuda_fp16.h>

#define N_NODES 100000
#define E_MAX   3200000
#define F_XD    64
#define F_UD    128
#define F_OUTD  128
#define B_GLOB  512
#define SCAN_B  1024

typedef unsigned long long ull;
typedef unsigned int uint32;

__device__ float g_agg[N_NODES * F_XD];
__device__ uint4 g_xh[N_NODES * 8];            // fp16 copy of x (row=128B)
__device__ float g_U[B_GLOB * 256];
__device__ int   g_is64;
__device__ int   g_deg[N_NODES];
__device__ int   g_rowptr[N_NODES];
__device__ int   g_cursor[N_NODES];
__device__ int   g_bsum[512];
__device__ int   g_boff[512];
__device__ uint2 g_edges[E_MAX];

__device__ __forceinline__ ull pack2(float a, float b) {
    ull r; asm("mov.b64 %0, {%1, %2};" : "=l"(r) : "f"(a), "f"(b)); return r;
}
__device__ __forceinline__ void ffma2(ull& d, ull a, ull b) {
    asm("fma.rn.f32x2 %0, %1, %2, %0;" : "+l"(d) : "l"(a), "l"(b));
}
__device__ __forceinline__ ull h2f2(unsigned h) {
    float2 f = __half22float2(*reinterpret_cast<__half2*>(&h));
    return pack2(f.x, f.y);
}
__device__ __forceinline__ uint32 f2tf32(float f) {
    uint32 r; asm("cvt.rna.tf32.f32 %0, %1;" : "=r"(r) : "f"(f)); return r;
}
__device__ __forceinline__ void mma_tf32(float* c, const uint32* a, uint32 b0, uint32 b1) {
    asm("mma.sync.aligned.m16n8k8.row.col.f32.tf32.tf32.f32 "
        "{%0,%1,%2,%3}, {%4,%5,%6,%7}, {%8,%9}, {%0,%1,%2,%3};"
        : "+f"(c[0]), "+f"(c[1]), "+f"(c[2]), "+f"(c[3])
        : "r"(a[0]), "r"(a[1]), "r"(a[2]), "r"(a[3]), "r"(b0), "r"(b1));
}

// ---------------------------------------------------------------------------
// zero degree counters + index-dtype probe
// ---------------------------------------------------------------------------
__global__ void zero_probe_kernel(const void* __restrict__ ei, int E, int N) {
    int i = blockIdx.x * blockDim.x + threadIdx.x;
    if (i < N) g_deg[i] = 0;
    if (i == 0) {
        const long long* p = (const long long*)ei;
        long long stride = (2LL * E) / 64;
        int ok = 1;
        for (int j = 0; j < 64; j++) {
            long long v = p[(long long)j * stride];
            if (v < 0 || v >= N) { ok = 0; break; }
        }
        g_is64 = ok;
    }
}

// ---------------------------------------------------------------------------
// convert x (fp32) -> g_xh (fp16 rows of 128B)
// ---------------------------------------------------------------------------
__global__ void xcvt_kernel(const float* __restrict__ x, int n) {   // n = N*8
    int i = blockIdx.x * blockDim.x + threadIdx.x;
    if (i >= n) return;
    float4 v0 = reinterpret_cast<const float4*>(x)[i * 2];
    float4 v1 = reinterpret_cast<const float4*>(x)[i * 2 + 1];
    __half2 h0 = __float22half2_rn(make_float2(v0.x, v0.y));
    __half2 h1 = __float22half2_rn(make_float2(v0.z, v0.w));
    __half2 h2 = __float22half2_rn(make_float2(v1.x, v1.y));
    __half2 h3 = __float22half2_rn(make_float2(v1.z, v1.w));
    uint4 o;
    o.x = *reinterpret_cast<unsigned*>(&h0);
    o.y = *reinterpret_cast<unsigned*>(&h1);
    o.z = *reinterpret_cast<unsigned*>(&h2);
    o.w = *reinterpret_cast<unsigned*>(&h3);
    g_xh[i] = o;
}

// ---------------------------------------------------------------------------
// in-degree histogram
// ---------------------------------------------------------------------------
__global__ void hist_kernel(const void* __restrict__ ei, int E) {
    const int is64 = g_is64;
    int t = blockIdx.x * blockDim.x + threadIdx.x;
    if (!is64 && (E & 3) == 0) {
        int n4 = E >> 2;
        if (t >= n4) return;
        int4 d4 = reinterpret_cast<const int4*>((const int*)ei + E)[t];
        atomicAdd(&g_deg[d4.x], 1);
        atomicAdd(&g_deg[d4.y], 1);
        atomicAdd(&g_deg[d4.z], 1);
        atomicAdd(&g_deg[d4.w], 1);
    } else {
        for (int e = t; e < E; e += gridDim.x * blockDim.x) {
            int d = is64 ? (int)((const long long*)ei)[E + e]
                         : ((const int*)ei)[E + e];
            atomicAdd(&g_deg[d], 1);
        }
    }
}

// ---------------------------------------------------------------------------
// Exclusive scan (3 phases)
// ---------------------------------------------------------------------------
__global__ void scan1_kernel(int N) {
    __shared__ int ss[256];
    int b = blockIdx.x, t = threadIdx.x;
    int base = b * SCAN_B + t * 4;
    int s = 0;
#pragma unroll
    for (int j = 0; j < 4; j++) { int idx = base + j; if (idx < N) s += g_deg[idx]; }
    ss[t] = s;
    __syncthreads();
    for (int off = 128; off > 0; off >>= 1) {
        if (t < off) ss[t] += ss[t + off];
        __syncthreads();
    }
    if (t == 0) g_bsum[b] = ss[0];
}

__global__ void scan2_kernel(int nblk) {
    __shared__ int ss[512];
    int t = threadIdx.x;
    int v = (t < nblk) ? g_bsum[t] : 0;
    ss[t] = v;
    __syncthreads();
    for (int off = 1; off < 512; off <<= 1) {
        int add = (t >= off) ? ss[t - off] : 0;
        __syncthreads();
        ss[t] += add;
        __syncthreads();
    }
    if (t < nblk) g_boff[t] = ss[t] - v;
}

__global__ void scan3_kernel(int N) {
    __shared__ int ss[256];
    int b = blockIdx.x, t = threadIdx.x;
    int base = b * SCAN_B + t * 4;
    int v[4]; int tsum = 0;
#pragma unroll
    for (int j = 0; j < 4; j++) {
        int idx = base + j;
        v[j] = (idx < N) ? g_deg[idx] : 0;
        tsum += v[j];
    }
    ss[t] = tsum;
    __syncthreads();
    for (int off = 1; off < 256; off <<= 1) {
        int add = (t >= off) ? ss[t - off] : 0;
        __syncthreads();
        ss[t] += add;
        __syncthreads();
    }
    int run = g_boff[b] + ss[t] - tsum;
#pragma unroll
    for (int j = 0; j < 4; j++) {
        int idx = base + j;
        if (idx < N) { g_rowptr[idx] = run; g_cursor[idx] = run; }
        run += v[j];
    }
}

// ---------------------------------------------------------------------------
// bucket edges by dest
// ---------------------------------------------------------------------------
__global__ void fill_kernel(const void*  __restrict__ ei,
                            const float* __restrict__ attr, int E) {
    const int is64 = g_is64;
    int e = blockIdx.x * blockDim.x + threadIdx.x;
    if (e >= E) return;
    int s, d;
    if (is64) { s = (int)((const long long*)ei)[e]; d = (int)((const long long*)ei)[E + e]; }
    else      { s = ((const int*)ei)[e];            d = ((const int*)ei)[E + e]; }
    int pos = atomicAdd(&g_cursor[d], 1);
    g_edges[pos] = make_uint2((unsigned)s, __float_as_uint(attr[e]));
}

// ---------------------------------------------------------------------------
// Aggregate (R12 champion): 4 dests/warp, 8 lanes/dest, LDG.128 fp16 gather
// ---------------------------------------------------------------------------
__global__ void __launch_bounds__(256)
agg_kernel(int N) {
    int t    = blockIdx.x * blockDim.x + threadIdx.x;
    int lane = t & 31;
    int grp  = lane >> 3;
    int l    = lane & 7;
    int w    = t >> 5;
    int d    = w * 4 + grp;

    int start = 0, deg = 0;
    if (d < N) { start = g_rowptr[d]; deg = g_deg[d]; }

    ull a0 = 0, a1 = 0, a2 = 0, a3 = 0;
    int i = 0;
    for (; i + 2 <= deg; i += 2) {
        uint2 e0 = g_edges[start + i];
        uint2 e1 = g_edges[start + i + 1];
        uint4 h0 = *(reinterpret_cast<const uint4*>(g_xh + (size_t)e0.x * 8) + l);
        uint4 h1 = *(reinterpret_cast<const uint4*>(g_xh + (size_t)e1.x * 8) + l);
        float w0 = __uint_as_float(e0.y), w1 = __uint_as_float(e1.y);
        ull w0p = pack2(w0, w0), w1p = pack2(w1, w1);
        ffma2(a0, h2f2(h0.x), w0p);
        ffma2(a1, h2f2(h0.y), w0p);
        ffma2(a2, h2f2(h0.z), w0p);
        ffma2(a3, h2f2(h0.w), w0p);
        ffma2(a0, h2f2(h1.x), w1p);
        ffma2(a1, h2f2(h1.y), w1p);
        ffma2(a2, h2f2(h1.z), w1p);
        ffma2(a3, h2f2(h1.w), w1p);
    }
    if (i < deg) {
        uint2 e0 = g_edges[start + i];
        uint4 h0 = *(reinterpret_cast<const uint4*>(g_xh + (size_t)e0.x * 8) + l);
        float w0 = __uint_as_float(e0.y);
        ull w0p = pack2(w0, w0);
        ffma2(a0, h2f2(h0.x), w0p);
        ffma2(a1, h2f2(h0.y), w0p);
        ffma2(a2, h2f2(h0.z), w0p);
        ffma2(a3, h2f2(h0.w), w0p);
    }

    if (d < N) {
        float2 f0 = *reinterpret_cast<float2*>(&a0);
        float2 f1 = *reinterpret_cast<float2*>(&a1);
        float2 f2 = *reinterpret_cast<float2*>(&a2);
        float2 f3 = *reinterpret_cast<float2*>(&a3);
        float* o = g_agg + (size_t)d * F_XD + l * 8;
        *reinterpret_cast<float4*>(o)     = make_float4(f0.x, f0.y, f1.x, f1.y);
        *reinterpret_cast<float4*>(o + 4) = make_float4(f2.x, f2.y, f3.x, f3.y);
    }
}

// ---------------------------------------------------------------------------
// u-projection: 4 batch rows per block (fp32, unchanged)
// ---------------------------------------------------------------------------
__global__ void u_proj_kernel(const float* __restrict__ u,
                              const float* __restrict__ WK, const float* __restrict__ bK,
                              const float* __restrict__ WQ, const float* __restrict__ bQ) {
    __shared__ float su[4][F_UD];
    int b0 = blockIdx.x * 4;
    int j  = threadIdx.x;
    for (int i = j; i < 4 * F_UD; i += 256)
        su[i >> 7][i & 127] = u[(b0 + (i >> 7)) * F_UD + (i & 127)];
    __syncthreads();

    const float* W   = (j < F_OUTD) ? WK : WQ;
    int          col = j & (F_OUTD - 1);
    float bias = (j < F_OUTD) ? bK[col] : bQ[col];
    float a0 = bias, a1 = bias, a2 = bias, a3 = bias;
#pragma unroll 4
    for (int k = 0; k < F_UD; k++) {
        float wv = W[(F_XD + k) * F_OUTD + col];
        a0 = fmaf(su[0][k], wv, a0);
        a1 = fmaf(su[1][k], wv, a1);
        a2 = fmaf(su[2][k], wv, a2);
        a3 = fmaf(su[3][k], wv, a3);
    }
    g_U[(b0 + 0) * 256 + j] = a0;
    g_U[(b0 + 1) * 256 + j] = a1;
    g_U[(b0 + 2) * 256 + j] = a2;
    g_U[(b0 + 3) * 256 + j] = a3;
}

// ---------------------------------------------------------------------------
// Fused projection v3 — tensor cores (mma.sync m16n8k8 tf32).
// Block: 256 thr (8 warps), tile 64 nodes x 256 cols.
// Warp: warp_m = wid&1 (32 nodes), warp_n = wid>>2... (wid>>1, 64 cols).
// sWt[c][k] stride 68, sA[n][k] stride 68 -> fragment LDS conflict-free.
// ---------------------------------------------------------------------------
#define WTS 68    // k-stride for both smem tiles (mult of 4; (4g+t)%32 distinct)

__global__ void __launch_bounds__(256, 1)
proj_kernel(const void* __restrict__ batch,
            const float* __restrict__ WK,
            const float* __restrict__ WQ,
            float* __restrict__ out, int N) {
    extern __shared__ uint32 shp[];
    uint32* sWt = shp;                    // [256][WTS] tf32 bits
    uint32* sA  = shp + 256 * WTS;        // [64][WTS]  tf32 bits
    __shared__ int sB[64];

    int tid   = threadIdx.x;
    int node0 = blockIdx.x * 64;

    // Stage W transposed + tf32: i -> (k, col-quad)
    for (int i = tid; i < 64 * 64; i += 256) {
        int k  = i >> 6;
        int jq = (i & 63) * 4;
        float4 v;
        if (jq < 128) v = *reinterpret_cast<const float4*>(WK + k * 128 + jq);
        else          v = *reinterpret_cast<const float4*>(WQ + k * 128 + (jq - 128));
        sWt[(jq + 0) * WTS + k] = f2tf32(v.x);
        sWt[(jq + 1) * WTS + k] = f2tf32(v.y);
        sWt[(jq + 2) * WTS + k] = f2tf32(v.z);
        sWt[(jq + 3) * WTS + k] = f2tf32(v.w);
    }
    // Stage A (row-major, no transpose) + tf32: i -> (node, k-quad)
    for (int i = tid; i < 64 * 16; i += 256) {
        int n  = i >> 4;
        int k4 = (i & 15) * 4;
        int gn = node0 + n;
        float4 v = (gn < N)
            ? *reinterpret_cast<const float4*>(g_agg + (size_t)gn * F_XD + k4)
            : make_float4(0.f, 0.f, 0.f, 0.f);
        uint4 o = make_uint4(f2tf32(v.x), f2tf32(v.y), f2tf32(v.z), f2tf32(v.w));
        *reinterpret_cast<uint4*>(sA + n * WTS + k4) = o;
    }
    if (tid < 64) {
        int gn = node0 + tid;
        int b = 0;
        if (gn < N) {
            if (g_is64) b = (int)((const long long*)batch)[gn];
            else        b = ((const int*)batch)[gn];
        }
        sB[tid] = b;
    }
    __syncthreads();

    int lane   = tid & 31;
    int wid    = tid >> 5;
    int warp_m = wid & 1;        // 2 x 32 nodes
    int warp_n = wid >> 1;       // 4 x 64 cols
    int g = lane >> 2;           // 0..7
    int t = lane & 3;            // 0..3

    float acc[2][8][4];
#pragma unroll
    for (int mt = 0; mt < 2; mt++)
#pragma unroll
        for (int nt = 0; nt < 8; nt++)
#pragma unroll
            for (int c = 0; c < 4; c++) acc[mt][nt][c] = 0.f;

#pragma unroll
    for (int ks = 0; ks < 8; ks++) {
        int k0 = ks * 8;
        uint32 a[2][4];
#pragma unroll
        for (int mt = 0; mt < 2; mt++) {
            int rb = warp_m * 32 + mt * 16;
            a[mt][0] = sA[(rb + g)     * WTS + k0 + t];
            a[mt][1] = sA[(rb + g + 8) * WTS + k0 + t];
            a[mt][2] = sA[(rb + g)     * WTS + k0 + t + 4];
            a[mt][3] = sA[(rb + g + 8) * WTS + k0 + t + 4];
        }
#pragma unroll
        for (int nt = 0; nt < 8; nt++) {
            int col = warp_n * 64 + nt * 8 + g;
            uint32 b0 = sWt[col * WTS + k0 + t];
            uint32 b1 = sWt[col * WTS + k0 + t + 4];
            mma_tf32(acc[0][nt], a[0], b0, b1);
            mma_tf32(acc[1][nt], a[1], b0, b1);
        }
    }

    // Epilogue: add U[batch[row]] and store. warp_n 0,1 -> K; 2,3 -> Q.
    float* ob = (warp_n < 2) ? out : (out + (size_t)N * 128);
    int    cb = (warp_n < 2) ? warp_n * 64 : (warp_n - 2) * 64;

#pragma unroll
    for (int mt = 0; mt < 2; mt++) {
        int rbase = warp_m * 32 + mt * 16 + g;
#pragma unroll
        for (int half = 0; half < 2; half++) {
            int rloc = rbase + half * 8;        // local node index
            int grow = node0 + rloc;
            if (grow < N) {
                const float* ur = g_U + sB[rloc] * 256 + (warp_n * 64) + 2 * t;
#pragma unroll
                for (int nt = 0; nt < 8; nt++) {
                    float2 uv = *reinterpret_cast<const float2*>(ur + nt * 8);
                    float2 res;
                    res.x = acc[mt][nt][half * 2 + 0] + uv.x;
                    res.y = acc[mt][nt][half * 2 + 1] + uv.y;
                    *reinterpret_cast<float2*>(ob + (size_t)grow * 128 + cb + nt * 8 + 2 * t) = res;
                }
            }
        }
    }
}

// ---------------------------------------------------------------------------
extern "C" void kernel_launch(void* const* d_in, const int* in_sizes, int n_in,
                              void* d_out, int out_size) {
    const float* x     = (const float*)d_in[0];
    const void*  ei    = d_in[1];
    const float* attr  = (const float*)d_in[2];
    const float* u     = (const float*)d_in[3];
    const void*  batch = d_in[4];
    const float* WK    = (const float*)d_in[5];
    const float* bK    = (const float*)d_in[6];
    const float* WQ    = (const float*)d_in[7];
    const float* bQ    = (const float*)d_in[8];
    float*       out   = (float*)d_out;

    int E = in_sizes[2];
    int N = in_sizes[4];
    int nblk = (N + SCAN_B - 1) / SCAN_B;

    zero_probe_kernel<<<(N + 255) / 256, 256>>>(ei, E, N);
    xcvt_kernel<<<(N * 8 + 255) / 256, 256>>>(x, N * 8);
    hist_kernel<<<((E >> 2) + 255) / 256, 256>>>(ei, E);
    scan1_kernel<<<nblk, 256>>>(N);
    scan2_kernel<<<1, 512>>>(nblk);
    scan3_kernel<<<nblk, 256>>>(N);
    fill_kernel<<<(E + 255) / 256, 256>>>(ei, attr, E);

    int nwarp = (N + 3) / 4;
    agg_kernel<<<(nwarp * 32 + 255) / 256, 256>>>(N);

    u_proj_kernel<<<B_GLOB / 4, 256>>>(u, WK, bK, WQ, bQ);

    int smem = (256 * WTS + 64 * WTS) * (int)sizeof(uint32);
    cudaFuncSetAttribute(proj_kernel, cudaFuncAttributeMaxDynamicSharedMemorySize, smem);
    proj_kernel<<<(N + 63) / 64, 256, smem>>>(batch, WK, WQ, out, N);
}

// round 14
// speedup vs baseline: 1.1086x; 1.1086x over previous
#include <cuda_runtime.h>
#include <cuda_fp16.h>

#define N_NODES 100000
#define E_MAX   3200000
#define F_XD    64
#define F_UD    128
#define F_OUTD  128
#define B_GLOB  512
#define SCAN_B  1024

typedef unsigned long long ull;
typedef unsigned int uint32;

__device__ float g_agg[N_NODES * F_XD];
__device__ uint4 g_xh[N_NODES * 8];            // fp16 copy of x (row=128B)
__device__ float g_U[B_GLOB * 256];
__device__ int   g_is64;
__device__ int   g_deg[N_NODES];
__device__ int   g_rowptr[N_NODES];
__device__ int   g_cursor[N_NODES];
__device__ int   g_bsum[512];
__device__ int   g_boff[512];
__device__ uint2 g_edges[E_MAX];

__device__ __forceinline__ ull pack2(float a, float b) {
    ull r; asm("mov.b64 %0, {%1, %2};" : "=l"(r) : "f"(a), "f"(b)); return r;
}
__device__ __forceinline__ void ffma2(ull& d, ull a, ull b) {
    asm("fma.rn.f32x2 %0, %1, %2, %0;" : "+l"(d) : "l"(a), "l"(b));
}
__device__ __forceinline__ ull h2f2(unsigned h) {
    float2 f = __half22float2(*reinterpret_cast<__half2*>(&h));
    return pack2(f.x, f.y);
}
__device__ __forceinline__ uint32 f2tf32(float f) {
    uint32 r; asm("cvt.rna.tf32.f32 %0, %1;" : "=r"(r) : "f"(f)); return r;
}
__device__ __forceinline__ void mma_tf32(float* c, const uint32* a, uint32 b0, uint32 b1) {
    asm("mma.sync.aligned.m16n8k8.row.col.f32.tf32.tf32.f32 "
        "{%0,%1,%2,%3}, {%4,%5,%6,%7}, {%8,%9}, {%0,%1,%2,%3};"
        : "+f"(c[0]), "+f"(c[1]), "+f"(c[2]), "+f"(c[3])
        : "r"(a[0]), "r"(a[1]), "r"(a[2]), "r"(a[3]), "r"(b0), "r"(b1));
}

// ---------------------------------------------------------------------------
// zero degree counters + index-dtype probe
// ---------------------------------------------------------------------------
__global__ void zero_probe_kernel(const void* __restrict__ ei, int E, int N) {
    int i = blockIdx.x * blockDim.x + threadIdx.x;
    if (i < N) g_deg[i] = 0;
    if (i == 0) {
        const long long* p = (const long long*)ei;
        long long stride = (2LL * E) / 64;
        int ok = 1;
        for (int j = 0; j < 64; j++) {
            long long v = p[(long long)j * stride];
            if (v < 0 || v >= N) { ok = 0; break; }
        }
        g_is64 = ok;
    }
}

// ---------------------------------------------------------------------------
// convert x (fp32) -> g_xh (fp16 rows of 128B)
// ---------------------------------------------------------------------------
__global__ void xcvt_kernel(const float* __restrict__ x, int n) {   // n = N*8
    int i = blockIdx.x * blockDim.x + threadIdx.x;
    if (i >= n) return;
    float4 v0 = reinterpret_cast<const float4*>(x)[i * 2];
    float4 v1 = reinterpret_cast<const float4*>(x)[i * 2 + 1];
    __half2 h0 = __float22half2_rn(make_float2(v0.x, v0.y));
    __half2 h1 = __float22half2_rn(make_float2(v0.z, v0.w));
    __half2 h2 = __float22half2_rn(make_float2(v1.x, v1.y));
    __half2 h3 = __float22half2_rn(make_float2(v1.z, v1.w));
    uint4 o;
    o.x = *reinterpret_cast<unsigned*>(&h0);
    o.y = *reinterpret_cast<unsigned*>(&h1);
    o.z = *reinterpret_cast<unsigned*>(&h2);
    o.w = *reinterpret_cast<unsigned*>(&h3);
    g_xh[i] = o;
}

// ---------------------------------------------------------------------------
// in-degree histogram
// ---------------------------------------------------------------------------
__global__ void hist_kernel(const void* __restrict__ ei, int E) {
    const int is64 = g_is64;
    int t = blockIdx.x * blockDim.x + threadIdx.x;
    if (!is64 && (E & 3) == 0) {
        int n4 = E >> 2;
        if (t >= n4) return;
        int4 d4 = reinterpret_cast<const int4*>((const int*)ei + E)[t];
        atomicAdd(&g_deg[d4.x], 1);
        atomicAdd(&g_deg[d4.y], 1);
        atomicAdd(&g_deg[d4.z], 1);
        atomicAdd(&g_deg[d4.w], 1);
    } else {
        for (int e = t; e < E; e += gridDim.x * blockDim.x) {
            int d = is64 ? (int)((const long long*)ei)[E + e]
                         : ((const int*)ei)[E + e];
            atomicAdd(&g_deg[d], 1);
        }
    }
}

// ---------------------------------------------------------------------------
// Exclusive scan (3 phases)
// ---------------------------------------------------------------------------
__global__ void scan1_kernel(int N) {
    __shared__ int ss[256];
    int b = blockIdx.x, t = threadIdx.x;
    int base = b * SCAN_B + t * 4;
    int s = 0;
#pragma unroll
    for (int j = 0; j < 4; j++) { int idx = base + j; if (idx < N) s += g_deg[idx]; }
    ss[t] = s;
    __syncthreads();
    for (int off = 128; off > 0; off >>= 1) {
        if (t < off) ss[t] += ss[t + off];
        __syncthreads();
    }
    if (t == 0) g_bsum[b] = ss[0];
}

__global__ void scan2_kernel(int nblk) {
    __shared__ int ss[512];
    int t = threadIdx.x;
    int v = (t < nblk) ? g_bsum[t] : 0;
    ss[t] = v;
    __syncthreads();
    for (int off = 1; off < 512; off <<= 1) {
        int add = (t >= off) ? ss[t - off] : 0;
        __syncthreads();
        ss[t] += add;
        __syncthreads();
    }
    if (t < nblk) g_boff[t] = ss[t] - v;
}

__global__ void scan3_kernel(int N) {
    __shared__ int ss[256];
    int b = blockIdx.x, t = threadIdx.x;
    int base = b * SCAN_B + t * 4;
    int v[4]; int tsum = 0;
#pragma unroll
    for (int j = 0; j < 4; j++) {
        int idx = base + j;
        v[j] = (idx < N) ? g_deg[idx] : 0;
        tsum += v[j];
    }
    ss[t] = tsum;
    __syncthreads();
    for (int off = 1; off < 256; off <<= 1) {
        int add = (t >= off) ? ss[t - off] : 0;
        __syncthreads();
        ss[t] += add;
        __syncthreads();
    }
    int run = g_boff[b] + ss[t] - tsum;
#pragma unroll
    for (int j = 0; j < 4; j++) {
        int idx = base + j;
        if (idx < N) { g_rowptr[idx] = run; g_cursor[idx] = run; }
        run += v[j];
    }
}

// ---------------------------------------------------------------------------
// bucket edges by dest
// ---------------------------------------------------------------------------
__global__ void fill_kernel(const void*  __restrict__ ei,
                            const float* __restrict__ attr, int E) {
    const int is64 = g_is64;
    int e = blockIdx.x * blockDim.x + threadIdx.x;
    if (e >= E) return;
    int s, d;
    if (is64) { s = (int)((const long long*)ei)[e]; d = (int)((const long long*)ei)[E + e]; }
    else      { s = ((const int*)ei)[e];            d = ((const int*)ei)[E + e]; }
    int pos = atomicAdd(&g_cursor[d], 1);
    g_edges[pos] = make_uint2((unsigned)s, __float_as_uint(attr[e]));
}

// ---------------------------------------------------------------------------
// Aggregate (R12 champion): 4 dests/warp, 8 lanes/dest, LDG.128 fp16 gather
// ---------------------------------------------------------------------------
__global__ void __launch_bounds__(256)
agg_kernel(int N) {
    int t    = blockIdx.x * blockDim.x + threadIdx.x;
    int lane = t & 31;
    int grp  = lane >> 3;
    int l    = lane & 7;
    int w    = t >> 5;
    int d    = w * 4 + grp;

    int start = 0, deg = 0;
    if (d < N) { start = g_rowptr[d]; deg = g_deg[d]; }

    ull a0 = 0, a1 = 0, a2 = 0, a3 = 0;
    int i = 0;
    for (; i + 2 <= deg; i += 2) {
        uint2 e0 = g_edges[start + i];
        uint2 e1 = g_edges[start + i + 1];
        uint4 h0 = *(reinterpret_cast<const uint4*>(g_xh + (size_t)e0.x * 8) + l);
        uint4 h1 = *(reinterpret_cast<const uint4*>(g_xh + (size_t)e1.x * 8) + l);
        float w0 = __uint_as_float(e0.y), w1 = __uint_as_float(e1.y);
        ull w0p = pack2(w0, w0), w1p = pack2(w1, w1);
        ffma2(a0, h2f2(h0.x), w0p);
        ffma2(a1, h2f2(h0.y), w0p);
        ffma2(a2, h2f2(h0.z), w0p);
        ffma2(a3, h2f2(h0.w), w0p);
        ffma2(a0, h2f2(h1.x), w1p);
        ffma2(a1, h2f2(h1.y), w1p);
        ffma2(a2, h2f2(h1.z), w1p);
        ffma2(a3, h2f2(h1.w), w1p);
    }
    if (i < deg) {
        uint2 e0 = g_edges[start + i];
        uint4 h0 = *(reinterpret_cast<const uint4*>(g_xh + (size_t)e0.x * 8) + l);
        float w0 = __uint_as_float(e0.y);
        ull w0p = pack2(w0, w0);
        ffma2(a0, h2f2(h0.x), w0p);
        ffma2(a1, h2f2(h0.y), w0p);
        ffma2(a2, h2f2(h0.z), w0p);
        ffma2(a3, h2f2(h0.w), w0p);
    }

    if (d < N) {
        float2 f0 = *reinterpret_cast<float2*>(&a0);
        float2 f1 = *reinterpret_cast<float2*>(&a1);
        float2 f2 = *reinterpret_cast<float2*>(&a2);
        float2 f3 = *reinterpret_cast<float2*>(&a3);
        float* o = g_agg + (size_t)d * F_XD + l * 8;
        *reinterpret_cast<float4*>(o)     = make_float4(f0.x, f0.y, f1.x, f1.y);
        *reinterpret_cast<float4*>(o + 4) = make_float4(f2.x, f2.y, f3.x, f3.y);
    }
}

// ---------------------------------------------------------------------------
// u-projection: 4 batch rows per block
// ---------------------------------------------------------------------------
__global__ void u_proj_kernel(const float* __restrict__ u,
                              const float* __restrict__ WK, const float* __restrict__ bK,
                              const float* __restrict__ WQ, const float* __restrict__ bQ) {
    __shared__ float su[4][F_UD];
    int b0 = blockIdx.x * 4;
    int j  = threadIdx.x;
    for (int i = j; i < 4 * F_UD; i += 256)
        su[i >> 7][i & 127] = u[(b0 + (i >> 7)) * F_UD + (i & 127)];
    __syncthreads();

    const float* W   = (j < F_OUTD) ? WK : WQ;
    int          col = j & (F_OUTD - 1);
    float bias = (j < F_OUTD) ? bK[col] : bQ[col];
    float a0 = bias, a1 = bias, a2 = bias, a3 = bias;
#pragma unroll 4
    for (int k = 0; k < F_UD; k++) {
        float wv = W[(F_XD + k) * F_OUTD + col];
        a0 = fmaf(su[0][k], wv, a0);
        a1 = fmaf(su[1][k], wv, a1);
        a2 = fmaf(su[2][k], wv, a2);
        a3 = fmaf(su[3][k], wv, a3);
    }
    g_U[(b0 + 0) * 256 + j] = a0;
    g_U[(b0 + 1) * 256 + j] = a1;
    g_U[(b0 + 2) * 256 + j] = a2;
    g_U[(b0 + 3) * 256 + j] = a3;
}

// ---------------------------------------------------------------------------
// Fused projection v4 — tf32 mma, FIXED layout:
//   sW k-major [64][264]: staging conflict-free (16B-apart uint4 stores),
//     B-fragment loads conflict-free (264 ≡ 8 mod 32 -> bank = 8t+8nt+g).
//   sA [64][68]: A-fragment bank = 4g+t, conflict-free (proven R13).
//   83KB smem, launch_bounds(256,2) -> 2 CTAs/SM.
// ---------------------------------------------------------------------------
#define WKS 264   // sW k-row stride (words)
#define ATS 68    // sA node-row stride (words)

__global__ void __launch_bounds__(256, 2)
proj_kernel(const void* __restrict__ batch,
            const float* __restrict__ WK,
            const float* __restrict__ WQ,
            float* __restrict__ out, int N) {
    extern __shared__ uint32 shp[];
    uint32* sW = shp;                     // [64][WKS] tf32 bits, k-major
    uint32* sA = shp + 64 * WKS;          // [64][ATS] tf32 bits, node-major
    __shared__ int sB[64];

    int tid   = threadIdx.x;
    int node0 = blockIdx.x * 64;

    // Stage W (k-major, no transpose) + tf32: i -> (k, col-quad)
    for (int i = tid; i < 64 * 64; i += 256) {
        int k  = i >> 6;
        int jq = (i & 63) * 4;
        float4 v;
        if (jq < 128) v = *reinterpret_cast<const float4*>(WK + k * 128 + jq);
        else          v = *reinterpret_cast<const float4*>(WQ + k * 128 + (jq - 128));
        *reinterpret_cast<uint4*>(sW + k * WKS + jq) =
            make_uint4(f2tf32(v.x), f2tf32(v.y), f2tf32(v.z), f2tf32(v.w));
    }
    // Stage A (node-major) + tf32: i -> (node, k-quad)
    for (int i = tid; i < 64 * 16; i += 256) {
        int n  = i >> 4;
        int k4 = (i & 15) * 4;
        int gn = node0 + n;
        float4 v = (gn < N)
            ? *reinterpret_cast<const float4*>(g_agg + (size_t)gn * F_XD + k4)
            : make_float4(0.f, 0.f, 0.f, 0.f);
        *reinterpret_cast<uint4*>(sA + n * ATS + k4) =
            make_uint4(f2tf32(v.x), f2tf32(v.y), f2tf32(v.z), f2tf32(v.w));
    }
    if (tid < 64) {
        int gn = node0 + tid;
        int b = 0;
        if (gn < N) {
            if (g_is64) b = (int)((const long long*)batch)[gn];
            else        b = ((const int*)batch)[gn];
        }
        sB[tid] = b;
    }
    __syncthreads();

    int lane   = tid & 31;
    int wid    = tid >> 5;
    int warp_m = wid & 1;        // 2 x 32 nodes
    int warp_n = wid >> 1;       // 4 x 64 cols
    int g = lane >> 2;           // 0..7
    int t = lane & 3;            // 0..3

    float acc[2][8][4];
#pragma unroll
    for (int mt = 0; mt < 2; mt++)
#pragma unroll
        for (int nt = 0; nt < 8; nt++)
#pragma unroll
            for (int c = 0; c < 4; c++) acc[mt][nt][c] = 0.f;

#pragma unroll
    for (int ks = 0; ks < 8; ks++) {
        int k0 = ks * 8;
        uint32 a[2][4];
#pragma unroll
        for (int mt = 0; mt < 2; mt++) {
            int rb = warp_m * 32 + mt * 16;
            a[mt][0] = sA[(rb + g)     * ATS + k0 + t];
            a[mt][1] = sA[(rb + g + 8) * ATS + k0 + t];
            a[mt][2] = sA[(rb + g)     * ATS + k0 + t + 4];
            a[mt][3] = sA[(rb + g + 8) * ATS + k0 + t + 4];
        }
#pragma unroll
        for (int nt = 0; nt < 8; nt++) {
            int col = warp_n * 64 + nt * 8 + g;
            uint32 b0 = sW[(k0 + t)     * WKS + col];
            uint32 b1 = sW[(k0 + t + 4) * WKS + col];
            mma_tf32(acc[0][nt], a[0], b0, b1);
            mma_tf32(acc[1][nt], a[1], b0, b1);
        }
    }

    // Epilogue: add U[batch[row]] and store. warp_n 0,1 -> K; 2,3 -> Q.
    float* ob = (warp_n < 2) ? out : (out + (size_t)N * 128);
    int    cb = (warp_n < 2) ? warp_n * 64 : (warp_n - 2) * 64;

#pragma unroll
    for (int mt = 0; mt < 2; mt++) {
        int rbase = warp_m * 32 + mt * 16 + g;
#pragma unroll
        for (int half = 0; half < 2; half++) {
            int rloc = rbase + half * 8;
            int grow = node0 + rloc;
            if (grow < N) {
                const float* ur = g_U + sB[rloc] * 256 + (warp_n * 64) + 2 * t;
#pragma unroll
                for (int nt = 0; nt < 8; nt++) {
                    float2 uv = *reinterpret_cast<const float2*>(ur + nt * 8);
                    float2 res;
                    res.x = acc[mt][nt][half * 2 + 0] + uv.x;
                    res.y = acc[mt][nt][half * 2 + 1] + uv.y;
                    *reinterpret_cast<float2*>(ob + (size_t)grow * 128 + cb + nt * 8 + 2 * t) = res;
                }
            }
        }
    }
}

// ---------------------------------------------------------------------------
extern "C" void kernel_launch(void* const* d_in, const int* in_sizes, int n_in,
                              void* d_out, int out_size) {
    const float* x     = (const float*)d_in[0];
    const void*  ei    = d_in[1];
    const float* attr  = (const float*)d_in[2];
    const float* u     = (const float*)d_in[3];
    const void*  batch = d_in[4];
    const float* WK    = (const float*)d_in[5];
    const float* bK    = (const float*)d_in[6];
    const float* WQ    = (const float*)d_in[7];
    const float* bQ    = (const float*)d_in[8];
    float*       out   = (float*)d_out;

    int E = in_sizes[2];
    int N = in_sizes[4];
    int nblk = (N + SCAN_B - 1) / SCAN_B;

    zero_probe_kernel<<<(N + 255) / 256, 256>>>(ei, E, N);
    xcvt_kernel<<<(N * 8 + 255) / 256, 256>>>(x, N * 8);
    hist_kernel<<<((E >> 2) + 255) / 256, 256>>>(ei, E);
    scan1_kernel<<<nblk, 256>>>(N);
    scan2_kernel<<<1, 512>>>(nblk);
    scan3_kernel<<<nblk, 256>>>(N);
    fill_kernel<<<(E + 255) / 256, 256>>>(ei, attr, E);

    int nwarp = (N + 3) / 4;
    agg_kernel<<<(nwarp * 32 + 255) / 256, 256>>>(N);

    u_proj_kernel<<<B_GLOB / 4, 256>>>(u, WK, bK, WQ, bQ);

    int smem = (64 * WKS + 64 * ATS) * (int)sizeof(uint32);
    cudaFuncSetAttribute(proj_kernel, cudaFuncAttributeMaxDynamicSharedMemorySize, smem);
    proj_kernel<<<(N + 63) / 64, 256, smem>>>(batch, WK, WQ, out, N);
}

// round 15
// speedup vs baseline: 1.1169x; 1.0074x over previous
#include <cuda_runtime.h>
#include <cuda_fp16.h>

#define N_NODES 100000
#define E_MAX   3200000
#define F_XD    64
#define F_UD    128
#define F_OUTD  128
#define B_GLOB  512
#define SCAN_B  1024

typedef unsigned long long ull;
typedef unsigned int uint32;

__device__ float g_agg[N_NODES * F_XD];
__device__ uint4 g_xh[N_NODES * 8];            // fp16 copy of x (row=128B)
__device__ float g_U[B_GLOB * 256];
__device__ int   g_is64;
__device__ int   g_deg[N_NODES];
__device__ int   g_rowptr[N_NODES];
__device__ int   g_cursor[N_NODES];
__device__ int   g_bsum[512];
__device__ int   g_boff[512];
__device__ uint2 g_edges[E_MAX];

__device__ __forceinline__ ull pack2(float a, float b) {
    ull r; asm("mov.b64 %0, {%1, %2};" : "=l"(r) : "f"(a), "f"(b)); return r;
}
__device__ __forceinline__ void ffma2(ull& d, ull a, ull b) {
    asm("fma.rn.f32x2 %0, %1, %2, %0;" : "+l"(d) : "l"(a), "l"(b));
}
__device__ __forceinline__ ull h2f2(unsigned h) {
    float2 f = __half22float2(*reinterpret_cast<__half2*>(&h));
    return pack2(f.x, f.y);
}
__device__ __forceinline__ uint32 f2tf32(float f) {
    uint32 r; asm("cvt.rna.tf32.f32 %0, %1;" : "=r"(r) : "f"(f)); return r;
}
__device__ __forceinline__ void mma_tf32(float* c, const uint32* a, uint32 b0, uint32 b1) {
    asm("mma.sync.aligned.m16n8k8.row.col.f32.tf32.tf32.f32 "
        "{%0,%1,%2,%3}, {%4,%5,%6,%7}, {%8,%9}, {%0,%1,%2,%3};"
        : "+f"(c[0]), "+f"(c[1]), "+f"(c[2]), "+f"(c[3])
        : "r"(a[0]), "r"(a[1]), "r"(a[2]), "r"(a[3]), "r"(b0), "r"(b1));
}

// ---------------------------------------------------------------------------
// zero degree counters + index-dtype probe
// ---------------------------------------------------------------------------
__global__ void zero_probe_kernel(const void* __restrict__ ei, int E, int N) {
    int i = blockIdx.x * blockDim.x + threadIdx.x;
    if (i < N) g_deg[i] = 0;
    if (i == 0) {
        const long long* p = (const long long*)ei;
        long long stride = (2LL * E) / 64;
        int ok = 1;
        for (int j = 0; j < 64; j++) {
            long long v = p[(long long)j * stride];
            if (v < 0 || v >= N) { ok = 0; break; }
        }
        g_is64 = ok;
    }
}

// ---------------------------------------------------------------------------
// convert x (fp32) -> g_xh (fp16 rows of 128B)
// ---------------------------------------------------------------------------
__global__ void xcvt_kernel(const float* __restrict__ x, int n) {   // n = N*8
    int i = blockIdx.x * blockDim.x + threadIdx.x;
    if (i >= n) return;
    float4 v0 = reinterpret_cast<const float4*>(x)[i * 2];
    float4 v1 = reinterpret_cast<const float4*>(x)[i * 2 + 1];
    __half2 h0 = __float22half2_rn(make_float2(v0.x, v0.y));
    __half2 h1 = __float22half2_rn(make_float2(v0.z, v0.w));
    __half2 h2 = __float22half2_rn(make_float2(v1.x, v1.y));
    __half2 h3 = __float22half2_rn(make_float2(v1.z, v1.w));
    uint4 o;
    o.x = *reinterpret_cast<unsigned*>(&h0);
    o.y = *reinterpret_cast<unsigned*>(&h1);
    o.z = *reinterpret_cast<unsigned*>(&h2);
    o.w = *reinterpret_cast<unsigned*>(&h3);
    g_xh[i] = o;
}

// ---------------------------------------------------------------------------
// in-degree histogram
// ---------------------------------------------------------------------------
__global__ void hist_kernel(const void* __restrict__ ei, int E) {
    const int is64 = g_is64;
    int t = blockIdx.x * blockDim.x + threadIdx.x;
    if (!is64 && (E & 3) == 0) {
        int n4 = E >> 2;
        if (t >= n4) return;
        int4 d4 = reinterpret_cast<const int4*>((const int*)ei + E)[t];
        atomicAdd(&g_deg[d4.x], 1);
        atomicAdd(&g_deg[d4.y], 1);
        atomicAdd(&g_deg[d4.z], 1);
        atomicAdd(&g_deg[d4.w], 1);
    } else {
        for (int e = t; e < E; e += gridDim.x * blockDim.x) {
            int d = is64 ? (int)((const long long*)ei)[E + e]
                         : ((const int*)ei)[E + e];
            atomicAdd(&g_deg[d], 1);
        }
    }
}

// ---------------------------------------------------------------------------
// Exclusive scan (3 phases)
// ---------------------------------------------------------------------------
__global__ void scan1_kernel(int N) {
    __shared__ int ss[256];
    int b = blockIdx.x, t = threadIdx.x;
    int base = b * SCAN_B + t * 4;
    int s = 0;
#pragma unroll
    for (int j = 0; j < 4; j++) { int idx = base + j; if (idx < N) s += g_deg[idx]; }
    ss[t] = s;
    __syncthreads();
    for (int off = 128; off > 0; off >>= 1) {
        if (t < off) ss[t] += ss[t + off];
        __syncthreads();
    }
    if (t == 0) g_bsum[b] = ss[0];
}

__global__ void scan2_kernel(int nblk) {
    __shared__ int ss[512];
    int t = threadIdx.x;
    int v = (t < nblk) ? g_bsum[t] : 0;
    ss[t] = v;
    __syncthreads();
    for (int off = 1; off < 512; off <<= 1) {
        int add = (t >= off) ? ss[t - off] : 0;
        __syncthreads();
        ss[t] += add;
        __syncthreads();
    }
    if (t < nblk) g_boff[t] = ss[t] - v;
}

__global__ void scan3_kernel(int N) {
    __shared__ int ss[256];
    int b = blockIdx.x, t = threadIdx.x;
    int base = b * SCAN_B + t * 4;
    int v[4]; int tsum = 0;
#pragma unroll
    for (int j = 0; j < 4; j++) {
        int idx = base + j;
        v[j] = (idx < N) ? g_deg[idx] : 0;
        tsum += v[j];
    }
    ss[t] = tsum;
    __syncthreads();
    for (int off = 1; off < 256; off <<= 1) {
        int add = (t >= off) ? ss[t - off] : 0;
        __syncthreads();
        ss[t] += add;
        __syncthreads();
    }
    int run = g_boff[b] + ss[t] - tsum;
#pragma unroll
    for (int j = 0; j < 4; j++) {
        int idx = base + j;
        if (idx < N) { g_rowptr[idx] = run; g_cursor[idx] = run; }
        run += v[j];
    }
}

// ---------------------------------------------------------------------------
// bucket edges by dest
// ---------------------------------------------------------------------------
__global__ void fill_kernel(const void*  __restrict__ ei,
                            const float* __restrict__ attr, int E) {
    const int is64 = g_is64;
    int e = blockIdx.x * blockDim.x + threadIdx.x;
    if (e >= E) return;
    int s, d;
    if (is64) { s = (int)((const long long*)ei)[e]; d = (int)((const long long*)ei)[E + e]; }
    else      { s = ((const int*)ei)[e];            d = ((const int*)ei)[E + e]; }
    int pos = atomicAdd(&g_cursor[d], 1);
    g_edges[pos] = make_uint2((unsigned)s, __float_as_uint(attr[e]));
}

// ---------------------------------------------------------------------------
// Aggregate (R12 champion): 4 dests/warp, 8 lanes/dest, LDG.128 fp16 gather
// ---------------------------------------------------------------------------
__global__ void __launch_bounds__(256)
agg_kernel(int N) {
    int t    = blockIdx.x * blockDim.x + threadIdx.x;
    int lane = t & 31;
    int grp  = lane >> 3;
    int l    = lane & 7;
    int w    = t >> 5;
    int d    = w * 4 + grp;

    int start = 0, deg = 0;
    if (d < N) { start = g_rowptr[d]; deg = g_deg[d]; }

    ull a0 = 0, a1 = 0, a2 = 0, a3 = 0;
    int i = 0;
    for (; i + 2 <= deg; i += 2) {
        uint2 e0 = g_edges[start + i];
        uint2 e1 = g_edges[start + i + 1];
        uint4 h0 = *(reinterpret_cast<const uint4*>(g_xh + (size_t)e0.x * 8) + l);
        uint4 h1 = *(reinterpret_cast<const uint4*>(g_xh + (size_t)e1.x * 8) + l);
        float w0 = __uint_as_float(e0.y), w1 = __uint_as_float(e1.y);
        ull w0p = pack2(w0, w0), w1p = pack2(w1, w1);
        ffma2(a0, h2f2(h0.x), w0p);
        ffma2(a1, h2f2(h0.y), w0p);
        ffma2(a2, h2f2(h0.z), w0p);
        ffma2(a3, h2f2(h0.w), w0p);
        ffma2(a0, h2f2(h1.x), w1p);
        ffma2(a1, h2f2(h1.y), w1p);
        ffma2(a2, h2f2(h1.z), w1p);
        ffma2(a3, h2f2(h1.w), w1p);
    }
    if (i < deg) {
        uint2 e0 = g_edges[start + i];
        uint4 h0 = *(reinterpret_cast<const uint4*>(g_xh + (size_t)e0.x * 8) + l);
        float w0 = __uint_as_float(e0.y);
        ull w0p = pack2(w0, w0);
        ffma2(a0, h2f2(h0.x), w0p);
        ffma2(a1, h2f2(h0.y), w0p);
        ffma2(a2, h2f2(h0.z), w0p);
        ffma2(a3, h2f2(h0.w), w0p);
    }

    if (d < N) {
        float2 f0 = *reinterpret_cast<float2*>(&a0);
        float2 f1 = *reinterpret_cast<float2*>(&a1);
        float2 f2 = *reinterpret_cast<float2*>(&a2);
        float2 f3 = *reinterpret_cast<float2*>(&a3);
        float* o = g_agg + (size_t)d * F_XD + l * 8;
        *reinterpret_cast<float4*>(o)     = make_float4(f0.x, f0.y, f1.x, f1.y);
        *reinterpret_cast<float4*>(o + 4) = make_float4(f2.x, f2.y, f3.x, f3.y);
    }
}

// ---------------------------------------------------------------------------
// u-projection: 4 batch rows per block
// ---------------------------------------------------------------------------
__global__ void u_proj_kernel(const float* __restrict__ u,
                              const float* __restrict__ WK, const float* __restrict__ bK,
                              const float* __restrict__ WQ, const float* __restrict__ bQ) {
    __shared__ float su[4][F_UD];
    int b0 = blockIdx.x * 4;
    int j  = threadIdx.x;
    for (int i = j; i < 4 * F_UD; i += 256)
        su[i >> 7][i & 127] = u[(b0 + (i >> 7)) * F_UD + (i & 127)];
    __syncthreads();

    const float* W   = (j < F_OUTD) ? WK : WQ;
    int          col = j & (F_OUTD - 1);
    float bias = (j < F_OUTD) ? bK[col] : bQ[col];
    float a0 = bias, a1 = bias, a2 = bias, a3 = bias;
#pragma unroll 4
    for (int k = 0; k < F_UD; k++) {
        float wv = W[(F_XD + k) * F_OUTD + col];
        a0 = fmaf(su[0][k], wv, a0);
        a1 = fmaf(su[1][k], wv, a1);
        a2 = fmaf(su[2][k], wv, a2);
        a3 = fmaf(su[3][k], wv, a3);
    }
    g_U[(b0 + 0) * 256 + j] = a0;
    g_U[(b0 + 1) * 256 + j] = a1;
    g_U[(b0 + 2) * 256 + j] = a2;
    g_U[(b0 + 3) * 256 + j] = a3;
}

// ---------------------------------------------------------------------------
// Fused projection v4 — tf32 mma, FIXED layout:
//   sW k-major [64][264]: staging conflict-free (16B-apart uint4 stores),
//     B-fragment loads conflict-free (264 ≡ 8 mod 32 -> bank = 8t+8nt+g).
//   sA [64][68]: A-fragment bank = 4g+t, conflict-free (proven R13).
//   83KB smem, launch_bounds(256,2) -> 2 CTAs/SM.
// ---------------------------------------------------------------------------
#define WKS 264   // sW k-row stride (words)
#define ATS 68    // sA node-row stride (words)

__global__ void __launch_bounds__(256, 2)
proj_kernel(const void* __restrict__ batch,
            const float* __restrict__ WK,
            const float* __restrict__ WQ,
            float* __restrict__ out, int N) {
    extern __shared__ uint32 shp[];
    uint32* sW = shp;                     // [64][WKS] tf32 bits, k-major
    uint32* sA = shp + 64 * WKS;          // [64][ATS] tf32 bits, node-major
    __shared__ int sB[64];

    int tid   = threadIdx.x;
    int node0 = blockIdx.x * 64;

    // Stage W (k-major, no transpose) + tf32: i -> (k, col-quad)
    for (int i = tid; i < 64 * 64; i += 256) {
        int k  = i >> 6;
        int jq = (i & 63) * 4;
        float4 v;
        if (jq < 128) v = *reinterpret_cast<const float4*>(WK + k * 128 + jq);
        else          v = *reinterpret_cast<const float4*>(WQ + k * 128 + (jq - 128));
        *reinterpret_cast<uint4*>(sW + k * WKS + jq) =
            make_uint4(f2tf32(v.x), f2tf32(v.y), f2tf32(v.z), f2tf32(v.w));
    }
    // Stage A (node-major) + tf32: i -> (node, k-quad)
    for (int i = tid; i < 64 * 16; i += 256) {
        int n  = i >> 4;
        int k4 = (i & 15) * 4;
        int gn = node0 + n;
        float4 v = (gn < N)
            ? *reinterpret_cast<const float4*>(g_agg + (size_t)gn * F_XD + k4)
            : make_float4(0.f, 0.f, 0.f, 0.f);
        *reinterpret_cast<uint4*>(sA + n * ATS + k4) =
            make_uint4(f2tf32(v.x), f2tf32(v.y), f2tf32(v.z), f2tf32(v.w));
    }
    if (tid < 64) {
        int gn = node0 + tid;
        int b = 0;
        if (gn < N) {
            if (g_is64) b = (int)((const long long*)batch)[gn];
            else        b = ((const int*)batch)[gn];
        }
        sB[tid] = b;
    }
    __syncthreads();

    int lane   = tid & 31;
    int wid    = tid >> 5;
    int warp_m = wid & 1;        // 2 x 32 nodes
    int warp_n = wid >> 1;       // 4 x 64 cols
    int g = lane >> 2;           // 0..7
    int t = lane & 3;            // 0..3

    float acc[2][8][4];
#pragma unroll
    for (int mt = 0; mt < 2; mt++)
#pragma unroll
        for (int nt = 0; nt < 8; nt++)
#pragma unroll
            for (int c = 0; c < 4; c++) acc[mt][nt][c] = 0.f;

#pragma unroll
    for (int ks = 0; ks < 8; ks++) {
        int k0 = ks * 8;
        uint32 a[2][4];
#pragma unroll
        for (int mt = 0; mt < 2; mt++) {
            int rb = warp_m * 32 + mt * 16;
            a[mt][0] = sA[(rb + g)     * ATS + k0 + t];
            a[mt][1] = sA[(rb + g + 8) * ATS + k0 + t];
            a[mt][2] = sA[(rb + g)     * ATS + k0 + t + 4];
            a[mt][3] = sA[(rb + g + 8) * ATS + k0 + t + 4];
        }
#pragma unroll
        for (int nt = 0; nt < 8; nt++) {
            int col = warp_n * 64 + nt * 8 + g;
            uint32 b0 = sW[(k0 + t)     * WKS + col];
            uint32 b1 = sW[(k0 + t + 4) * WKS + col];
            mma_tf32(acc[0][nt], a[0], b0, b1);
            mma_tf32(acc[1][nt], a[1], b0, b1);
        }
    }

    // Epilogue: add U[batch[row]] and store. warp_n 0,1 -> K; 2,3 -> Q.
    float* ob = (warp_n < 2) ? out : (out + (size_t)N * 128);
    int    cb = (warp_n < 2) ? warp_n * 64 : (warp_n - 2) * 64;

#pragma unroll
    for (int mt = 0; mt < 2; mt++) {
        int rbase = warp_m * 32 + mt * 16 + g;
#pragma unroll
        for (int half = 0; half < 2; half++) {
            int rloc = rbase + half * 8;
            int grow = node0 + rloc;
            if (grow < N) {
                const float* ur = g_U + sB[rloc] * 256 + (warp_n * 64) + 2 * t;
#pragma unroll
                for (int nt = 0; nt < 8; nt++) {
                    float2 uv = *reinterpret_cast<const float2*>(ur + nt * 8);
                    float2 res;
                    res.x = acc[mt][nt][half * 2 + 0] + uv.x;
                    res.y = acc[mt][nt][half * 2 + 1] + uv.y;
                    *reinterpret_cast<float2*>(ob + (size_t)grow * 128 + cb + nt * 8 + 2 * t) = res;
                }
            }
        }
    }
}

// ---------------------------------------------------------------------------
extern "C" void kernel_launch(void* const* d_in, const int* in_sizes, int n_in,
                              void* d_out, int out_size) {
    const float* x     = (const float*)d_in[0];
    const void*  ei    = d_in[1];
    const float* attr  = (const float*)d_in[2];
    const float* u     = (const float*)d_in[3];
    const void*  batch = d_in[4];
    const float* WK    = (const float*)d_in[5];
    const float* bK    = (const float*)d_in[6];
    const float* WQ    = (const float*)d_in[7];
    const float* bQ    = (const float*)d_in[8];
    float*       out   = (float*)d_out;

    int E = in_sizes[2];
    int N = in_sizes[4];
    int nblk = (N + SCAN_B - 1) / SCAN_B;

    zero_probe_kernel<<<(N + 255) / 256, 256>>>(ei, E, N);
    xcvt_kernel<<<(N * 8 + 255) / 256, 256>>>(x, N * 8);
    hist_kernel<<<((E >> 2) + 255) / 256, 256>>>(ei, E);
    scan1_kernel<<<nblk, 256>>>(N);
    scan2_kernel<<<1, 512>>>(nblk);
    scan3_kernel<<<nblk, 256>>>(N);
    fill_kernel<<<(E + 255) / 256, 256>>>(ei, attr, E);

    int nwarp = (N + 3) / 4;
    agg_kernel<<<(nwarp * 32 + 255) / 256, 256>>>(N);

    u_proj_kernel<<<B_GLOB / 4, 256>>>(u, WK, bK, WQ, bQ);

    int smem = (64 * WKS + 64 * ATS) * (int)sizeof(uint32);
    cudaFuncSetAttribute(proj_kernel, cudaFuncAttributeMaxDynamicSharedMemorySize, smem);
    proj_kernel<<<(N + 63) / 64, 256, smem>>>(batch, WK, WQ, out, N);
}